// round 13
// baseline (speedup 1.0000x reference)
#include <cuda_runtime.h>

// AdaptiveFeaturePooling: 4-level ROIAlign (out=14, sr=2) + max over levels.
// SINGLE fused kernel, grid = R + 512:
//  builders (bid < R): bilinear tables + mask + release-published worklist;
//    signal g_bdone; skip-fill own ROI slice; then all 8 warps JOIN the
//    warp-level consumer pool.
//  consumers (bid >= R): each WARP independently pops worklist tickets
//    (no block syncs). Per entry: 8 batched rounds x (32 channels, 16
//    independent LDGs/thread), shfl butterfly over 4-lane groups, store.
// Builders come first in the grid and never wait -> no scheduling deadlock.
// Counters/worklist self-reset (graph-replay deterministic).

#define OUTSZ  14
#define CELLS  196
#define CH     256
#define GSAMP  28           // OUTSZ*2
#define MAXROI 512
#define CGRID  512
#define MAXENT (MAXROI * CELLS)
#define NF4    ((CH * CELLS) / 4)   // 12544 float4 per ROI slice
#define NGRP   (NF4 / CH)           // 49 float4 groups per channel

__device__ float4 g_tab[MAXROI][4][2][GSAMP];  // {w0,w1,lo,hi}
__device__ unsigned g_work[MAXENT];            // (r<<12)|(cell<<4)|m, 0=unpublished
__device__ int g_count;
__device__ int g_bdone;
__device__ int g_pop;
__device__ int g_ticket;

__device__ __forceinline__ int ldacq_s32(const int* p)
{
    int v; asm volatile("ld.acquire.gpu.s32 %0, [%1];" : "=r"(v) : "l"(p)); return v;
}
__device__ __forceinline__ unsigned ldacq_u32(const unsigned* p)
{
    unsigned v; asm volatile("ld.acquire.gpu.u32 %0, [%1];" : "=r"(v) : "l"(p)); return v;
}
__device__ __forceinline__ void strel_u32(unsigned* p, unsigned v)
{
    asm volatile("st.release.gpu.u32 [%0], %1;" :: "l"(p), "r"(v) : "memory");
}

// Warp-level pop-and-compute loop. Each warp works independently.
__device__ __forceinline__ void consume_warp(
    const float* __restrict__ f0, const float* __restrict__ f1,
    const float* __restrict__ f2, const float* __restrict__ f3,
    float* __restrict__ out, int R)
{
    const int lane = threadIdx.x & 31;
    const int xi   = lane & 3;          // x-tap index
    const int c8   = lane >> 2;         // channel sub-index 0..7
    const float* fl[4] = { f0, f1, f2, f3 };

    for (;;) {
        int t = -1;
        if (lane == 0) {
            // Avoid pointless atomics once the list is drained.
            bool done = (ldacq_s32(&g_bdone) == R);
            if (done && *(volatile int*)&g_pop >= *(volatile int*)&g_count) {
                t = -1;
            } else {
                t = atomicAdd(&g_pop, 1);
            }
        }
        t = __shfl_sync(0xFFFFFFFFu, t, 0);
        if (t < 0 || t >= MAXENT) break;

        // lane 0 polls until published (or drained), then all lanes
        // acquire-read the entry themselves (ordering for g_tab reads).
        unsigned w0l = 0;
        if (lane == 0) {
            w0l = ldacq_u32(&g_work[t]);
            while (w0l == 0u) {
                if (ldacq_s32(&g_bdone) == R) { w0l = ldacq_u32(&g_work[t]); break; }
                __nanosleep(32);
                w0l = ldacq_u32(&g_work[t]);
            }
        }
        w0l = __shfl_sync(0xFFFFFFFFu, w0l, 0);
        if (w0l == 0u) break;            // t >= final count: drained
        const unsigned w = ldacq_u32(&g_work[t]);   // per-lane acquire

        int r    = (int)(w >> 12);
        int cell = (int)((w >> 4) & 0xFF);
        unsigned m = w & 0xF;
        int py = cell / OUTSZ;
        int px = cell - py * OUTSZ;
        int sy = 2 * py, sx = 2 * px;

        float* obase = out + (size_t)r * (CH * CELLS) + cell;

        #pragma unroll 1
        for (int b = 0; b < 8; ++b) {    // 8 rounds x 32 channels
            const int cb = c8 + 32 * b;  // channels cb, cb+8, cb+16, cb+24
            float best[4] = {0.f, 0.f, 0.f, 0.f};

            #pragma unroll
            for (int l = 0; l < 4; ++l) {
                if (m & (1u << l)) {
                    const int W = 224 >> l;
                    float4 ty0 = g_tab[r][l][0][sy];
                    float4 ty1 = g_tab[r][l][0][sy + 1];
                    float4 tx0 = g_tab[r][l][1][sx];
                    float4 tx1 = g_tab[r][l][1][sx + 1];

                    float wx; int x;
                    if (xi == 0)      { wx = tx0.x; x = __float_as_int(tx0.z); }
                    else if (xi == 1) { wx = tx0.y; x = __float_as_int(tx0.w); }
                    else if (xi == 2) { wx = tx1.x; x = __float_as_int(tx1.z); }
                    else              { wx = tx1.y; x = __float_as_int(tx1.w); }

                    int y0 = __float_as_int(ty0.z) * W;
                    int y1 = __float_as_int(ty0.w) * W;
                    int y2 = __float_as_int(ty1.z) * W;
                    int y3 = __float_as_int(ty1.w) * W;

                    // 16 independent LDGs, front-batched (one latency round).
                    float v[4][4];
                    #pragma unroll
                    for (int u = 0; u < 4; ++u) {
                        const float* fc = fl[l] + (size_t)(cb + 8 * u) * (W * W);
                        v[u][0] = fc[y0 + x];
                        v[u][1] = fc[y1 + x];
                        v[u][2] = fc[y2 + x];
                        v[u][3] = fc[y3 + x];
                    }
                    #pragma unroll
                    for (int u = 0; u < 4; ++u) {
                        float s = wx * (ty0.x * v[u][0] + ty0.y * v[u][1]
                                      + ty1.x * v[u][2] + ty1.y * v[u][3]);
                        s += __shfl_xor_sync(0xFFFFFFFFu, s, 1);
                        s += __shfl_xor_sync(0xFFFFFFFFu, s, 2);
                        best[u] = fmaxf(best[u], s * 0.25f);
                    }
                }
            }
            if (xi == 0) {
                #pragma unroll
                for (int u = 0; u < 4; ++u)
                    obase[(size_t)(cb + 8 * u) * CELLS] = best[u];
            }
        }

        if (lane == 0) g_work[t] = 0u;   // re-zero for next graph replay
    }
}

__global__ __launch_bounds__(256, 4)
void afp_fused(const float* __restrict__ f0, const float* __restrict__ f1,
               const float* __restrict__ f2, const float* __restrict__ f3,
               const float* __restrict__ rois, int R, float* __restrict__ out)
{
    const int tid = threadIdx.x;
    const int bid = blockIdx.x;

    if (bid < R) {
        // ============================ BUILDER ============================
        __shared__ float s_w0[4][2][GSAMP];
        __shared__ float s_w1[4][2][GSAMP];
        __shared__ unsigned char s_m[CELLS];
        __shared__ unsigned char s_anyv[NGRP];

        const int r = bid;

        // Phase A: bilinear prep (reference fp32 op order, exactly).
        if (tid < 4 * 2 * GSAMP) {
            int l   = tid / (2 * GSAMP);
            int rem = tid - l * (2 * GSAMP);
            int a   = rem / GSAMP;       // 0=y, 1=x
            int j   = rem - a * GSAMP;

            float p1 = rois[r * 4 + (a == 0 ? 1 : 0)];
            float p2 = rois[r * 4 + (a == 0 ? 3 : 2)];
            #pragma unroll
            for (int i = 3; i >= 0; --i) {
                if (i >= l) {
                    float s = (float)(28 << i);
                    p1 = __fmul_rn(p1, s);
                    p2 = __fmul_rn(p2, s);
                }
            }
            float len  = fmaxf(__fadd_rn(p2, -p1), 1.0f);
            float t    = __fdiv_rn(len, 14.0f);
            float step = ((float)j + 0.5f) * 0.5f;
            float c    = __fadd_rn(p1, __fmul_rn(step, t));

            int L = 224 >> l;
            bool valid = (c >= -1.0f) && (c <= (float)L);
            c = fminf(fmaxf(c, 0.0f), (float)(L - 1));
            float lo   = floorf(c);
            float frac = __fadd_rn(c, -lo);
            int loi = (int)lo;
            int hii = loi + 1;
            if (loi >= L - 1) { loi = L - 1; hii = L - 1; frac = 0.0f; }
            float v  = valid ? 1.0f : 0.0f;
            float w0 = (1.0f - frac) * v;
            float w1 = frac * v;
            s_w0[l][a][j] = w0;
            s_w1[l][a][j] = w1;
            g_tab[r][l][a][j] = make_float4(w0, w1, __int_as_float(loi), __int_as_float(hii));
        }
        __syncthreads();

        // Phase B: mask + publish worklist entries (cumulative release).
        if (tid < CELLS) {
            int py = tid / OUTSZ;
            int px = tid - py * OUTSZ;
            unsigned m = 0;
            #pragma unroll
            for (int l = 0; l < 4; ++l) {
                float wy = s_w0[l][0][2*py]   + s_w1[l][0][2*py]
                         + s_w0[l][0][2*py+1] + s_w1[l][0][2*py+1];
                float wx = s_w0[l][1][2*px]   + s_w1[l][1][2*px]
                         + s_w0[l][1][2*px+1] + s_w1[l][1][2*px+1];
                if (wy > 0.0f && wx > 0.0f) m |= (1u << l);
            }
            s_m[tid] = (unsigned char)m;
            if (m) {
                int pos = atomicAdd(&g_count, 1);
                strel_u32(&g_work[pos],
                          ((unsigned)r << 12) | ((unsigned)tid << 4) | m);
            }
        }
        __syncthreads();

        if (tid == 0) {
            __threadfence();
            atomicAdd(&g_bdone, 1);
        }

        if (tid < NGRP) {
            int k = tid * 4;
            s_anyv[tid] = (unsigned char)(s_m[k] | s_m[k+1] | s_m[k+2] | s_m[k+3]);
        }
        __syncthreads();

        // Skip-fill: zero all invalid cells of this ROI's slice.
        float* obase = out + (size_t)r * (CH * CELLS);
        float4* o4 = reinterpret_cast<float4*>(obase);
        const float4 z4 = make_float4(0.f, 0.f, 0.f, 0.f);
        int k = tid % NGRP;
        #pragma unroll 4
        for (int i = tid; i < NF4; i += 256) {
            if (!s_anyv[k]) {
                o4[i] = z4;
            } else {
                int cell0 = k * 4;
                float* p = obase + i * 4;
                #pragma unroll
                for (int q = 0; q < 4; ++q)
                    if (!s_m[cell0 + q]) p[q] = 0.0f;
            }
            k += 256 % NGRP;             // 11
            if (k >= NGRP) k -= NGRP;
        }
        // Builders' warps join the consumer pool after the fill.
        consume_warp(f0, f1, f2, f3, out, R);
    } else {
        // ============================ CONSUMER ===========================
        consume_warp(f0, f1, f2, f3, out, R);
    }

    // Self-reset: last block zeroes all counters for the next replay.
    __syncthreads();
    if (tid == 0) {
        int t = atomicAdd(&g_ticket, 1);
        if (t == R + CGRID - 1) {
            g_count  = 0;
            g_bdone  = 0;
            g_pop    = 0;
            g_ticket = 0;
        }
    }
}

extern "C" void kernel_launch(void* const* d_in, const int* in_sizes, int n_in,
                              void* d_out, int out_size)
{
    const float* f0   = (const float*)d_in[0];
    const float* f1   = (const float*)d_in[1];
    const float* f2   = (const float*)d_in[2];
    const float* f3   = (const float*)d_in[3];
    const float* rois = (const float*)d_in[4];
    int R = in_sizes[4] / 4;

    afp_fused<<<R + CGRID, 256>>>(f0, f1, f2, f3, rois, R, (float*)d_out);
}

// round 14
// speedup vs baseline: 1.4475x; 1.4475x over previous
#include <cuda_runtime.h>

// AdaptiveFeaturePooling: 4-level ROIAlign (out=14, sr=2) + max over levels.
// SINGLE fused kernel, grid = R + 512:
//  builders (bid < R): tables + mask + publish worklist; signal g_bdone;
//    skip-fill own ROI slice; then join consumer pool.
//  consumers (bid >= R): ONE cheap block-level wait for g_bdone==R (tid 0
//    polls at ~1us granularity), then warps pop tickets (no per-entry
//    polling -- everything is published) and process entries with batched
//    gathers (unroll 2 rounds => 32 LDGs in flight).
// Builders never wait and fit in wave 1 -> no deadlock. Counters/worklist
// self-reset for graph replay.

#define OUTSZ  14
#define CELLS  196
#define CH     256
#define GSAMP  28           // OUTSZ*2
#define MAXROI 512
#define CGRID  512
#define MAXENT (MAXROI * CELLS)
#define NF4    ((CH * CELLS) / 4)   // 12544 float4 per ROI slice
#define NGRP   (NF4 / CH)           // 49 float4 groups per channel

__device__ float4 g_tab[MAXROI][4][2][GSAMP];  // {w0,w1,lo,hi}
__device__ unsigned g_work[MAXENT];            // (r<<12)|(cell<<4)|m
__device__ int g_count;
__device__ int g_bdone;
__device__ int g_pop;
__device__ int g_ticket;

__device__ __forceinline__ int ldacq_s32(const int* p)
{
    int v; asm volatile("ld.acquire.gpu.s32 %0, [%1];" : "=r"(v) : "l"(p)); return v;
}

// Warp-level pop-and-compute. Called only after g_bdone == R was observed
// (so g_work/g_tab are fully published and plain loads are safe).
__device__ __forceinline__ void consume_warp(
    const float* __restrict__ f0, const float* __restrict__ f1,
    const float* __restrict__ f2, const float* __restrict__ f3,
    float* __restrict__ out, int n)
{
    const int lane = threadIdx.x & 31;
    const int xi   = lane & 3;          // x-tap index
    const int c8   = lane >> 2;         // channel sub-index 0..7
    const float* fl[4] = { f0, f1, f2, f3 };

    for (;;) {
        int t = 0;
        if (lane == 0) t = atomicAdd(&g_pop, 1);
        t = __shfl_sync(0xFFFFFFFFu, t, 0);
        if (t >= n) break;

        const unsigned w = g_work[t];

        int r    = (int)(w >> 12);
        int cell = (int)((w >> 4) & 0xFF);
        unsigned m = w & 0xF;
        int py = cell / OUTSZ;
        int px = cell - py * OUTSZ;
        int sy = 2 * py, sx = 2 * px;

        float* obase = out + (size_t)r * (CH * CELLS) + cell;

        #pragma unroll 2
        for (int b = 0; b < 8; ++b) {    // 8 rounds x 32 channels
            const int cb = c8 + 32 * b;  // channels cb, cb+8, cb+16, cb+24
            float best[4] = {0.f, 0.f, 0.f, 0.f};

            #pragma unroll
            for (int l = 0; l < 4; ++l) {
                if (m & (1u << l)) {
                    const int W = 224 >> l;
                    float4 ty0 = g_tab[r][l][0][sy];
                    float4 ty1 = g_tab[r][l][0][sy + 1];
                    float4 tx0 = g_tab[r][l][1][sx];
                    float4 tx1 = g_tab[r][l][1][sx + 1];

                    float wx; int x;
                    if (xi == 0)      { wx = tx0.x; x = __float_as_int(tx0.z); }
                    else if (xi == 1) { wx = tx0.y; x = __float_as_int(tx0.w); }
                    else if (xi == 2) { wx = tx1.x; x = __float_as_int(tx1.z); }
                    else              { wx = tx1.y; x = __float_as_int(tx1.w); }

                    int y0 = __float_as_int(ty0.z) * W;
                    int y1 = __float_as_int(ty0.w) * W;
                    int y2 = __float_as_int(ty1.z) * W;
                    int y3 = __float_as_int(ty1.w) * W;

                    // 16 independent LDGs, front-batched.
                    float v[4][4];
                    #pragma unroll
                    for (int u = 0; u < 4; ++u) {
                        const float* fc = fl[l] + (size_t)(cb + 8 * u) * (W * W);
                        v[u][0] = fc[y0 + x];
                        v[u][1] = fc[y1 + x];
                        v[u][2] = fc[y2 + x];
                        v[u][3] = fc[y3 + x];
                    }
                    #pragma unroll
                    for (int u = 0; u < 4; ++u) {
                        float s = wx * (ty0.x * v[u][0] + ty0.y * v[u][1]
                                      + ty1.x * v[u][2] + ty1.y * v[u][3]);
                        s += __shfl_xor_sync(0xFFFFFFFFu, s, 1);
                        s += __shfl_xor_sync(0xFFFFFFFFu, s, 2);
                        best[u] = fmaxf(best[u], s * 0.25f);
                    }
                }
            }
            if (xi == 0) {
                #pragma unroll
                for (int u = 0; u < 4; ++u)
                    obase[(size_t)(cb + 8 * u) * CELLS] = best[u];
            }
        }

        if (lane == 0) g_work[t] = 0u;   // re-zero for next graph replay
    }
}

__global__ __launch_bounds__(256, 4)
void afp_fused(const float* __restrict__ f0, const float* __restrict__ f1,
               const float* __restrict__ f2, const float* __restrict__ f3,
               const float* __restrict__ rois, int R, float* __restrict__ out)
{
    __shared__ int s_n;
    const int tid = threadIdx.x;
    const int bid = blockIdx.x;

    if (bid < R) {
        // ============================ BUILDER ============================
        __shared__ float s_w0[4][2][GSAMP];
        __shared__ float s_w1[4][2][GSAMP];
        __shared__ unsigned char s_m[CELLS];
        __shared__ unsigned char s_anyv[NGRP];

        const int r = bid;

        // Phase A: bilinear prep (reference fp32 op order, exactly).
        if (tid < 4 * 2 * GSAMP) {
            int l   = tid / (2 * GSAMP);
            int rem = tid - l * (2 * GSAMP);
            int a   = rem / GSAMP;       // 0=y, 1=x
            int j   = rem - a * GSAMP;

            float p1 = rois[r * 4 + (a == 0 ? 1 : 0)];
            float p2 = rois[r * 4 + (a == 0 ? 3 : 2)];
            #pragma unroll
            for (int i = 3; i >= 0; --i) {
                if (i >= l) {
                    float s = (float)(28 << i);
                    p1 = __fmul_rn(p1, s);
                    p2 = __fmul_rn(p2, s);
                }
            }
            float len  = fmaxf(__fadd_rn(p2, -p1), 1.0f);
            float t    = __fdiv_rn(len, 14.0f);
            float step = ((float)j + 0.5f) * 0.5f;
            float c    = __fadd_rn(p1, __fmul_rn(step, t));

            int L = 224 >> l;
            bool valid = (c >= -1.0f) && (c <= (float)L);
            c = fminf(fmaxf(c, 0.0f), (float)(L - 1));
            float lo   = floorf(c);
            float frac = __fadd_rn(c, -lo);
            int loi = (int)lo;
            int hii = loi + 1;
            if (loi >= L - 1) { loi = L - 1; hii = L - 1; frac = 0.0f; }
            float v  = valid ? 1.0f : 0.0f;
            float w0 = (1.0f - frac) * v;
            float w1 = frac * v;
            s_w0[l][a][j] = w0;
            s_w1[l][a][j] = w1;
            g_tab[r][l][a][j] = make_float4(w0, w1, __int_as_float(loi), __int_as_float(hii));
        }
        __syncthreads();

        // Phase B: mask + publish worklist entries.
        if (tid < CELLS) {
            int py = tid / OUTSZ;
            int px = tid - py * OUTSZ;
            unsigned m = 0;
            #pragma unroll
            for (int l = 0; l < 4; ++l) {
                float wy = s_w0[l][0][2*py]   + s_w1[l][0][2*py]
                         + s_w0[l][0][2*py+1] + s_w1[l][0][2*py+1];
                float wx = s_w0[l][1][2*px]   + s_w1[l][1][2*px]
                         + s_w0[l][1][2*px+1] + s_w1[l][1][2*px+1];
                if (wy > 0.0f && wx > 0.0f) m |= (1u << l);
            }
            s_m[tid] = (unsigned char)m;
            if (m) {
                int pos = atomicAdd(&g_count, 1);
                g_work[pos] = ((unsigned)r << 12) | ((unsigned)tid << 4) | m;
            }
        }
        __syncthreads();

        // Publish: all writes above visible before the bdone increment.
        if (tid == 0) {
            __threadfence();
            atomicAdd(&g_bdone, 1);
        }

        if (tid < NGRP) {
            int k = tid * 4;
            s_anyv[tid] = (unsigned char)(s_m[k] | s_m[k+1] | s_m[k+2] | s_m[k+3]);
        }
        __syncthreads();

        // Skip-fill: zero all invalid cells of this ROI's slice.
        float* obase = out + (size_t)r * (CH * CELLS);
        float4* o4 = reinterpret_cast<float4*>(obase);
        const float4 z4 = make_float4(0.f, 0.f, 0.f, 0.f);
        int k = tid % NGRP;
        #pragma unroll 4
        for (int i = tid; i < NF4; i += 256) {
            if (!s_anyv[k]) {
                o4[i] = z4;
            } else {
                int cell0 = k * 4;
                float* p = obase + i * 4;
                #pragma unroll
                for (int q = 0; q < 4; ++q)
                    if (!s_m[cell0 + q]) p[q] = 0.0f;
            }
            k += 256 % NGRP;             // 11
            if (k >= NGRP) k -= NGRP;
        }

        // Join consumer pool (list is long drained by now; 1 atomic/warp).
        if (tid == 0) s_n = g_count;     // bdone==R guaranteed: we published too
        __syncthreads();
        consume_warp(f0, f1, f2, f3, out, s_n);
    } else {
        // ============================ CONSUMER ===========================
        // ONE cheap block-level wait: tid 0 polls at ~1us granularity.
        if (tid == 0) {
            while (ldacq_s32(&g_bdone) < R) __nanosleep(1024);
            s_n = g_count;               // final (all builders published)
        }
        __syncthreads();
        consume_warp(f0, f1, f2, f3, out, s_n);
    }

    // Self-reset: last block zeroes all counters for the next replay.
    __syncthreads();
    if (tid == 0) {
        int t = atomicAdd(&g_ticket, 1);
        if (t == R + CGRID - 1) {
            g_count  = 0;
            g_bdone  = 0;
            g_pop    = 0;
            g_ticket = 0;
        }
    }
}

extern "C" void kernel_launch(void* const* d_in, const int* in_sizes, int n_in,
                              void* d_out, int out_size)
{
    const float* f0   = (const float*)d_in[0];
    const float* f1   = (const float*)d_in[1];
    const float* f2   = (const float*)d_in[2];
    const float* f3   = (const float*)d_in[3];
    const float* rois = (const float*)d_in[4];
    int R = in_sizes[4] / 4;

    afp_fused<<<R + CGRID, 256>>>(f0, f1, f2, f3, rois, R, (float*)d_out);
}